// round 1
// baseline (speedup 1.0000x reference)
#include <cuda_runtime.h>

#define BATCH 2
#define NC 4096
#define NF 16384
#define CC 256
#define CF 128
#define CO 256
#define KTOT 384  // CC + CF

// ---------------- scratch (device globals; no allocations allowed) ----------
__device__ float g_Yc[BATCH * CO * NC];   // Wc @ Fc  : [B, Co, Nc]
__device__ int   g_idx[BATCH * NF];       // nearest coarse index per fine point
__device__ float g_scale[CO];
__device__ float g_shift[CO];

// ---------------- packed f32x2 helpers (sm_100+) ----------------------------
typedef unsigned long long u64;

__device__ __forceinline__ u64 pack2(float lo, float hi) {
    u64 r;
    asm("mov.b64 %0,{%1,%2};" : "=l"(r) : "f"(lo), "f"(hi));
    return r;
}
__device__ __forceinline__ void unpack2(u64 v, float& lo, float& hi) {
    asm("mov.b64 {%0,%1},%2;" : "=f"(lo), "=f"(hi) : "l"(v));
}
__device__ __forceinline__ void fma2(u64& d, u64 a, u64 b) {
    asm("fma.rn.f32x2 %0,%1,%2,%0;" : "+l"(d) : "l"(a), "l"(b));
}

union V4 {
    float4 f;
    u64 d[2];
};

// ============================================================================
// K1: nearest coarse neighbor per fine point (brute force, smem-tiled)
// grid (NF/128, BATCH), block 128. Two 2048-point halves (32KB static smem).
// d(p, c) = |c|^2 - 2 p.c   (drops |p|^2, same argmin; strict < keeps first idx)
// ============================================================================
__global__ void nn_kernel(const float* __restrict__ xyzc,
                          const float* __restrict__ xyzf) {
    __shared__ float4 sc[2048];

    const int b = blockIdx.y;
    const int f = blockIdx.x * 128 + threadIdx.x;
    const float* p = xyzf + ((size_t)b * NF + f) * 3;
    const float px = -2.0f * p[0];
    const float py = -2.0f * p[1];
    const float pz = -2.0f * p[2];

    float best = 3.4e38f;
    int bi = 0;

    const float* xb = xyzc + (size_t)b * NC * 3;
    for (int half = 0; half < 2; half++) {
        // load 2048 coarse points (x, y, z, |c|^2)
        for (int j = threadIdx.x; j < 2048; j += 128) {
            const float* c = xb + (size_t)(half * 2048 + j) * 3;
            float x = c[0], y = c[1], z = c[2];
            sc[j] = make_float4(x, y, z, x * x + y * y + z * z);
        }
        __syncthreads();

        const int base = half * 2048;
#pragma unroll 4
        for (int j = 0; j < 2048; j += 2) {
            float4 c0 = sc[j];
            float4 c1 = sc[j + 1];
            float d0 = fmaf(px, c0.x, c0.w);
            d0 = fmaf(py, c0.y, d0);
            d0 = fmaf(pz, c0.z, d0);
            float d1 = fmaf(px, c1.x, c1.w);
            d1 = fmaf(py, c1.y, d1);
            d1 = fmaf(pz, c1.z, d1);
            float m = fminf(d0, d1);
            if (m < best) {
                best = m;
                bi = (d0 <= d1) ? (base + j) : (base + j + 1);
            }
        }
        __syncthreads();
    }
    g_idx[b * NF + f] = bi;
}

// ============================================================================
// GEMM (register-tiled, packed f32x2):  out[b,m,n] = sum_k W[m, WOFF+k] * F[b,k,n]
// BM=BN=128, BK=16, 256 threads, 8x8 per thread (n packed in f32x2 pairs).
// GATHER=true additionally adds g_Yc[b, m, idx[n]] and writes to dout (raw y).
// ============================================================================
#define BM 128
#define BN 128
#define BK 16
#define AST 132  // padded row stride for As (conflict-free, 16B-aligned reads)

template <int N, int KDIM, int WOFF, bool GATHER>
__global__ __launch_bounds__(256) void gemm_kernel(const float* __restrict__ W,
                                                   const float* __restrict__ F,
                                                   float* __restrict__ dout) {
    __shared__ float As[BK * AST];  // As[k][m]
    __shared__ float Bs[BK * BN];   // Bs[k][n]
    __shared__ int sidx[BN];

    const int b = blockIdx.z;
    const int mBase = blockIdx.y * BM;
    const int nBase = blockIdx.x * BN;
    const int t = threadIdx.x;
    const int tx = t & 15;   // n tile:  n0 = tx*8
    const int ty = t >> 4;   // m tile:  m0 = ty*8

    if (GATHER) {
        if (t < BN) sidx[t] = g_idx[b * NF + nBase + t];
    }

    u64 acc[8][4];
#pragma unroll
    for (int i = 0; i < 8; i++)
#pragma unroll
        for (int jp = 0; jp < 4; jp++) acc[i][jp] = 0ULL;

    const float* Wp = W + (size_t)mBase * KTOT + WOFF;
    const float* Fp = F + (size_t)b * KDIM * N + nBase;

    for (int k0 = 0; k0 < KDIM; k0 += BK) {
        // --- load A tile (transpose W[m][k] -> As[k][m]) : 2048 elements
#pragma unroll
        for (int it = 0; it < 8; it++) {
            int l = t + it * 256;  // 0..2047
            int m = l >> 4;
            int k = l & 15;
            As[k * AST + m] = Wp[(size_t)m * KTOT + (k0 + k)];
        }
        // --- load B tile: Bs[k][n], coalesced along n
        {
            int n = t & 127;
            int kh = (t >> 7) * 8;
            const float* fp = Fp + (size_t)(k0 + kh) * N + n;
            float r[8];
#pragma unroll
            for (int j = 0; j < 8; j++) r[j] = fp[(size_t)j * N];
#pragma unroll
            for (int j = 0; j < 8; j++) Bs[(kh + j) * BN + n] = r[j];
        }
        __syncthreads();

#pragma unroll
        for (int k = 0; k < BK; k++) {
            float4 a0 = *(const float4*)&As[k * AST + ty * 8];
            float4 a1 = *(const float4*)&As[k * AST + ty * 8 + 4];
            V4 b0, b1;
            b0.f = *(const float4*)&Bs[k * BN + tx * 8];
            b1.f = *(const float4*)&Bs[k * BN + tx * 8 + 4];
            u64 B2[4] = {b0.d[0], b0.d[1], b1.d[0], b1.d[1]};
            float A[8] = {a0.x, a0.y, a0.z, a0.w, a1.x, a1.y, a1.z, a1.w};
#pragma unroll
            for (int i = 0; i < 8; i++) {
                u64 ad = pack2(A[i], A[i]);
#pragma unroll
                for (int jp = 0; jp < 4; jp++) fma2(acc[i][jp], ad, B2[jp]);
            }
        }
        __syncthreads();
    }

    // --- epilogue
#pragma unroll
    for (int i = 0; i < 8; i++) {
        const int m = mBase + ty * 8 + i;
        float v[8];
#pragma unroll
        for (int jp = 0; jp < 4; jp++) {
            float lo, hi;
            unpack2(acc[i][jp], lo, hi);
            v[jp * 2] = lo;
            v[jp * 2 + 1] = hi;
        }
        if (GATHER) {
            const float* ycrow = g_Yc + ((size_t)b * CO + m) * NC;
#pragma unroll
            for (int jj = 0; jj < 8; jj++) v[jj] += ycrow[sidx[tx * 8 + jj]];
            float* orow = dout + ((size_t)b * CO + m) * NF + nBase + tx * 8;
            *(float4*)&orow[0] = make_float4(v[0], v[1], v[2], v[3]);
            *(float4*)&orow[4] = make_float4(v[4], v[5], v[6], v[7]);
        } else {
            float* orow = g_Yc + ((size_t)b * CO + m) * NC + nBase + tx * 8;
            *(float4*)&orow[0] = make_float4(v[0], v[1], v[2], v[3]);
            *(float4*)&orow[4] = make_float4(v[4], v[5], v[6], v[7]);
        }
    }
}

// ============================================================================
// K4: per-channel mean/var over (B, Nf); fold gamma/beta into scale/shift.
// Deterministic (fixed-order per-thread partials + smem tree). grid CO, block 256.
// ============================================================================
__global__ void stats_kernel(const float* __restrict__ y,
                             const float* __restrict__ gamma,
                             const float* __restrict__ beta) {
    const int o = blockIdx.x;
    const int t = threadIdx.x;
    float s = 0.f, ss = 0.f;
#pragma unroll
    for (int b = 0; b < BATCH; b++) {
        const float4* row = (const float4*)(y + ((size_t)b * CO + o) * NF);
        for (int i = t; i < NF / 4; i += 256) {
            float4 v = row[i];
            s += v.x + v.y + v.z + v.w;
            ss += v.x * v.x + v.y * v.y + v.z * v.z + v.w * v.w;
        }
    }
    __shared__ float sm[256];
    __shared__ float sm2[256];
    sm[t] = s;
    sm2[t] = ss;
    __syncthreads();
    for (int off = 128; off > 0; off >>= 1) {
        if (t < off) {
            sm[t] += sm[t + off];
            sm2[t] += sm2[t + off];
        }
        __syncthreads();
    }
    if (t == 0) {
        const float invn = 1.0f / (BATCH * NF);
        float mean = sm[0] * invn;
        float var = sm2[0] * invn - mean * mean;
        var = fmaxf(var, 0.0f);
        float r = rsqrtf(var + 1e-5f);
        float sc = gamma[o] * r;
        g_scale[o] = sc;
        g_shift[o] = beta[o] - mean * sc;
    }
}

// ============================================================================
// K5: y = relu(y * scale[o] + shift[o]) in place, float4 vectorized.
// ============================================================================
__global__ void norm_kernel(float* __restrict__ y) {
    const size_t i = (size_t)blockIdx.x * blockDim.x + threadIdx.x;  // float4 idx
    const int o = (int)((i >> 12) & (CO - 1));                       // NF/4 = 4096 = 2^12
    const float sc = g_scale[o];
    const float sh = g_shift[o];
    float4 v = ((const float4*)y)[i];
    v.x = fmaxf(fmaf(v.x, sc, sh), 0.0f);
    v.y = fmaxf(fmaf(v.y, sc, sh), 0.0f);
    v.z = fmaxf(fmaf(v.z, sc, sh), 0.0f);
    v.w = fmaxf(fmaf(v.w, sc, sh), 0.0f);
    ((float4*)y)[i] = v;
}

// ============================================================================
extern "C" void kernel_launch(void* const* d_in, const int* in_sizes, int n_in,
                              void* d_out, int out_size) {
    const float* xyzc  = (const float*)d_in[0];  // [2, 4096, 3]
    const float* fc    = (const float*)d_in[1];  // [2, 256, 4096]
    const float* xyzf  = (const float*)d_in[2];  // [2, 16384, 3]
    const float* ff    = (const float*)d_in[3];  // [2, 128, 16384]
    const float* W     = (const float*)d_in[4];  // [256, 384]
    const float* gamma = (const float*)d_in[5];  // [256]
    const float* beta  = (const float*)d_in[6];  // [256]
    float* out = (float*)d_out;                  // [2, 256, 16384]

    (void)in_sizes; (void)n_in; (void)out_size;

    // 1) nearest-neighbor indices
    nn_kernel<<<dim3(NF / 128, BATCH), 128>>>(xyzc, xyzf);

    // 2) Yc = W[:, 0:256] @ Fc   -> g_Yc [B, Co, Nc]
    gemm_kernel<NC, CC, 0, false>
        <<<dim3(NC / BN, CO / BM, BATCH), 256>>>(W, fc, out);

    // 3) y = W[:, 256:384] @ Ff + gather(Yc, idx)  -> d_out (raw, pre-BN)
    gemm_kernel<NF, CF, CC, true>
        <<<dim3(NF / BN, CO / BM, BATCH), 256>>>(W, ff, out);

    // 4) per-channel BN stats -> scale/shift
    stats_kernel<<<CO, 256>>>(out, gamma, beta);

    // 5) normalize + relu in place
    norm_kernel<<<(BATCH * CO * NF / 4) / 256, 256>>>(out);
}

// round 2
// speedup vs baseline: 1.0395x; 1.0395x over previous
#include <cuda_runtime.h>

#define BATCH 2
#define NC 4096
#define NF 16384
#define CC 256
#define CF 128
#define CO 256
#define KTOT 384  // CC + CF
#define NBLKF (NF / 128)   // 128 fine n-blocks

// ---------------- scratch (device globals; no allocations allowed) ----------
__device__ float g_Yc[BATCH * CO * NC];   // Wc @ Fc  : [B, Co, Nc]
__device__ int   g_idx[BATCH * NF];       // nearest coarse index per fine point
__device__ float g_ps [BATCH * CO * NBLKF];   // per-block partial sums
__device__ float g_pss[BATCH * CO * NBLKF];   // per-block partial sumsq
__device__ float g_scale[CO];
__device__ float g_shift[CO];

// ---------------- packed f32x2 helpers (sm_100+) ----------------------------
typedef unsigned long long u64;

__device__ __forceinline__ void unpack2(u64 v, float& lo, float& hi) {
    asm("mov.b64 {%0,%1},%2;" : "=f"(lo), "=f"(hi) : "l"(v));
}
__device__ __forceinline__ void fma2(u64& d, u64 a, u64 b) {
    asm("fma.rn.f32x2 %0,%1,%2,%0;" : "+l"(d) : "l"(a), "l"(b));
}

union V4 {
    float4 f;
    u64 d[2];
};

// ============================================================================
// K1: nearest coarse neighbor per fine point (brute force, smem-tiled)
// ============================================================================
__global__ void nn_kernel(const float* __restrict__ xyzc,
                          const float* __restrict__ xyzf) {
    __shared__ float4 sc[2048];

    const int b = blockIdx.y;
    const int f = blockIdx.x * 128 + threadIdx.x;
    const float* p = xyzf + ((size_t)b * NF + f) * 3;
    const float px = -2.0f * p[0];
    const float py = -2.0f * p[1];
    const float pz = -2.0f * p[2];

    float best = 3.4e38f;
    int bi = 0;

    const float* xb = xyzc + (size_t)b * NC * 3;
    for (int half = 0; half < 2; half++) {
        for (int j = threadIdx.x; j < 2048; j += 128) {
            const float* c = xb + (size_t)(half * 2048 + j) * 3;
            float x = c[0], y = c[1], z = c[2];
            sc[j] = make_float4(x, y, z, x * x + y * y + z * z);
        }
        __syncthreads();

        const int base = half * 2048;
#pragma unroll 4
        for (int j = 0; j < 2048; j += 2) {
            float4 c0 = sc[j];
            float4 c1 = sc[j + 1];
            float d0 = fmaf(px, c0.x, c0.w);
            d0 = fmaf(py, c0.y, d0);
            d0 = fmaf(pz, c0.z, d0);
            float d1 = fmaf(px, c1.x, c1.w);
            d1 = fmaf(py, c1.y, d1);
            d1 = fmaf(pz, c1.z, d1);
            float m = fminf(d0, d1);
            if (m < best) {
                best = m;
                bi = (d0 <= d1) ? (base + j) : (base + j + 1);
            }
        }
        __syncthreads();
    }
    g_idx[b * NF + f] = bi;
}

// ============================================================================
// GEMM (register-tiled, packed f32x2):  out[b,m,n] = sum_k W[m, WOFF+k]*F[b,k,n]
// BM=BN=128, BK=16, 256 threads, 8x8 per thread split into 4-wide halves:
//   m in {ty*4..+3} u {64+ty*4..+3},  n in {tx*4..+3} u {64+tx*4..+3}
// A tile stored DUPLICATED in smem as (a,a) float2 pairs -> no pack2 in loop.
// GATHER=true: adds g_Yc[b,m,idx[n]], writes raw y to dout, and emits
// per-block BN partial sums (fused stats).
// ============================================================================
#define BM 128
#define BN 128
#define BK 16
#define AST2 130  // float2 row stride for duplicated A (16B-aligned, low conflict)

template <int N, int KDIM, int WOFF, bool GATHER>
__global__ __launch_bounds__(256) void gemm_kernel(const float* __restrict__ W,
                                                   const float* __restrict__ F,
                                                   float* __restrict__ dout) {
    __shared__ float2 As2[BK * AST2];  // As2[k][m] = (w, w)
    __shared__ float  Bs[BK * BN];     // Bs[k][n]
    __shared__ int    sidx[BN];

    const int b = blockIdx.z;
    const int mBase = blockIdx.y * BM;
    const int nBase = blockIdx.x * BN;
    const int t = threadIdx.x;
    const int tx = t & 15;
    const int ty = t >> 4;

    if (GATHER) {
        if (t < BN) sidx[t] = g_idx[b * NF + nBase + t];
    }

    u64 acc[8][4];
#pragma unroll
    for (int i = 0; i < 8; i++)
#pragma unroll
        for (int jp = 0; jp < 4; jp++) acc[i][jp] = 0ULL;

    const float* Wp = W + (size_t)mBase * KTOT + WOFF;
    const float* Fp = F + (size_t)b * KDIM * N + nBase;

    // A-tile load mapping: thread t handles k = t&15, m-group = t>>4 (8 m each)
    const int ak = t & 15;
    const int am0 = (t >> 4) * 8;

    for (int k0 = 0; k0 < KDIM; k0 += BK) {
        // --- A tile: W[m][k0+ak] -> As2[ak][m] duplicated
#pragma unroll
        for (int j = 0; j < 8; j++) {
            float w = Wp[(size_t)(am0 + j) * KTOT + (k0 + ak)];
            As2[ak * AST2 + am0 + j] = make_float2(w, w);
        }
        // --- B tile: Bs[k][n], coalesced along n
        {
            int n = t & 127;
            int kh = (t >> 7) * 8;
            const float* fp = Fp + (size_t)(k0 + kh) * N + n;
            float r[8];
#pragma unroll
            for (int j = 0; j < 8; j++) r[j] = fp[(size_t)j * N];
#pragma unroll
            for (int j = 0; j < 8; j++) Bs[(kh + j) * BN + n] = r[j];
        }
        __syncthreads();

#pragma unroll
        for (int k = 0; k < BK; k++) {
            const float2* arow = As2 + k * AST2;
            V4 a0, a1, a2, a3, b0, b1;
            a0.f = *(const float4*)&arow[ty * 4];          // pairs m: ty*4, ty*4+1
            a1.f = *(const float4*)&arow[ty * 4 + 2];      //         ty*4+2, +3
            a2.f = *(const float4*)&arow[64 + ty * 4];
            a3.f = *(const float4*)&arow[64 + ty * 4 + 2];
            b0.f = *(const float4*)&Bs[k * BN + tx * 4];        // n pairs tx*4..
            b1.f = *(const float4*)&Bs[k * BN + 64 + tx * 4];
            u64 A2[8] = {a0.d[0], a0.d[1], a1.d[0], a1.d[1],
                         a2.d[0], a2.d[1], a3.d[0], a3.d[1]};
            u64 B2[4] = {b0.d[0], b0.d[1], b1.d[0], b1.d[1]};
#pragma unroll
            for (int i = 0; i < 8; i++)
#pragma unroll
                for (int jp = 0; jp < 4; jp++) fma2(acc[i][jp], A2[i], B2[jp]);
        }
        __syncthreads();
    }

    // --- epilogue
    float ps[8], pss[8];
#pragma unroll
    for (int i = 0; i < 8; i++) {
        const int m = mBase + ((i < 4) ? (ty * 4 + i) : (64 + ty * 4 + (i - 4)));
        float v[8];
#pragma unroll
        for (int jp = 0; jp < 4; jp++) {
            float lo, hi;
            unpack2(acc[i][jp], lo, hi);
            v[jp * 2] = lo;
            v[jp * 2 + 1] = hi;
        }
        // n mapping: v[0..3] -> nBase+tx*4+{0..3},  v[4..7] -> nBase+64+tx*4+{0..3}
        if (GATHER) {
            const float* ycrow = g_Yc + ((size_t)b * CO + m) * NC;
#pragma unroll
            for (int jj = 0; jj < 4; jj++) {
                v[jj]     += ycrow[sidx[tx * 4 + jj]];
                v[4 + jj] += ycrow[sidx[64 + tx * 4 + jj]];
            }
            float* orow = dout + ((size_t)b * CO + m) * NF + nBase;
            *(float4*)&orow[tx * 4]      = make_float4(v[0], v[1], v[2], v[3]);
            *(float4*)&orow[64 + tx * 4] = make_float4(v[4], v[5], v[6], v[7]);
            // fused BN partial stats (raw y)
            float s = 0.f, ss = 0.f;
#pragma unroll
            for (int jj = 0; jj < 8; jj++) {
                s += v[jj];
                ss += v[jj] * v[jj];
            }
            ps[i] = s;
            pss[i] = ss;
        } else {
            float* orow = g_Yc + ((size_t)b * CO + m) * NC + nBase;
            *(float4*)&orow[tx * 4]      = make_float4(v[0], v[1], v[2], v[3]);
            *(float4*)&orow[64 + tx * 4] = make_float4(v[4], v[5], v[6], v[7]);
        }
    }

    if (GATHER) {
        // reduce over the 16 lanes (same ty -> same channel set), width-16 shuffle
#pragma unroll
        for (int i = 0; i < 8; i++) {
#pragma unroll
            for (int off = 8; off > 0; off >>= 1) {
                ps[i]  += __shfl_down_sync(0xffffffffu, ps[i], off, 16);
                pss[i] += __shfl_down_sync(0xffffffffu, pss[i], off, 16);
            }
        }
        if (tx == 0) {
#pragma unroll
            for (int i = 0; i < 8; i++) {
                const int m = mBase + ((i < 4) ? (ty * 4 + i) : (64 + ty * 4 + (i - 4)));
                g_ps [((size_t)b * CO + m) * NBLKF + blockIdx.x] = ps[i];
                g_pss[((size_t)b * CO + m) * NBLKF + blockIdx.x] = pss[i];
            }
        }
    }
}

// ============================================================================
// K4: finish BN stats from partials. One warp per channel.
// grid CO/8, block 256 (8 warps). Deterministic fixed-order reduction.
// ============================================================================
__global__ void stats2_kernel(const float* __restrict__ gamma,
                              const float* __restrict__ beta) {
    const int o = blockIdx.x * 8 + (threadIdx.x >> 5);
    const int lane = threadIdx.x & 31;
    float s = 0.f, ss = 0.f;
#pragma unroll
    for (int j = 0; j < 8; j++) {
        int p = lane + j * 32;           // 0..255 over (b, nblk)
        int b = p >> 7;
        int nblk = p & 127;
        size_t off = ((size_t)b * CO + o) * NBLKF + nblk;
        s += g_ps[off];
        ss += g_pss[off];
    }
#pragma unroll
    for (int off = 16; off > 0; off >>= 1) {
        s  += __shfl_down_sync(0xffffffffu, s, off);
        ss += __shfl_down_sync(0xffffffffu, ss, off);
    }
    if (lane == 0) {
        const float invn = 1.0f / (BATCH * NF);
        float mean = s * invn;
        float var = ss * invn - mean * mean;
        var = fmaxf(var, 0.0f);
        float r = rsqrtf(var + 1e-5f);
        float sc = gamma[o] * r;
        g_scale[o] = sc;
        g_shift[o] = beta[o] - mean * sc;
    }
}

// ============================================================================
// K5: y = relu(y * scale[o] + shift[o]) in place, float4 vectorized.
// ============================================================================
__global__ void norm_kernel(float* __restrict__ y) {
    const size_t i = (size_t)blockIdx.x * blockDim.x + threadIdx.x;  // float4 idx
    const int o = (int)((i >> 12) & (CO - 1));                       // NF/4 = 4096
    const float sc = g_scale[o];
    const float sh = g_shift[o];
    float4 v = ((const float4*)y)[i];
    v.x = fmaxf(fmaf(v.x, sc, sh), 0.0f);
    v.y = fmaxf(fmaf(v.y, sc, sh), 0.0f);
    v.z = fmaxf(fmaf(v.z, sc, sh), 0.0f);
    v.w = fmaxf(fmaf(v.w, sc, sh), 0.0f);
    ((float4*)y)[i] = v;
}

// ============================================================================
extern "C" void kernel_launch(void* const* d_in, const int* in_sizes, int n_in,
                              void* d_out, int out_size) {
    const float* xyzc  = (const float*)d_in[0];  // [2, 4096, 3]
    const float* fc    = (const float*)d_in[1];  // [2, 256, 4096]
    const float* xyzf  = (const float*)d_in[2];  // [2, 16384, 3]
    const float* ff    = (const float*)d_in[3];  // [2, 128, 16384]
    const float* W     = (const float*)d_in[4];  // [256, 384]
    const float* gamma = (const float*)d_in[5];  // [256]
    const float* beta  = (const float*)d_in[6];  // [256]
    float* out = (float*)d_out;                  // [2, 256, 16384]

    (void)in_sizes; (void)n_in; (void)out_size;

    nn_kernel<<<dim3(NF / 128, BATCH), 128>>>(xyzc, xyzf);

    gemm_kernel<NC, CC, 0, false>
        <<<dim3(NC / BN, CO / BM, BATCH), 256>>>(W, fc, out);

    gemm_kernel<NF, CF, CC, true>
        <<<dim3(NF / BN, CO / BM, BATCH), 256>>>(W, ff, out);

    stats2_kernel<<<CO / 8, 256>>>(gamma, beta);

    norm_kernel<<<(BATCH * CO * NF / 4) / 256, 256>>>(out);
}

// round 4
// speedup vs baseline: 1.4084x; 1.3549x over previous
#include <cuda_runtime.h>
#include <cuda_bf16.h>
#include <cstdint>

#define BATCH 2
#define NC 4096
#define NF 16384
#define CC 256
#define CF 128
#define CO 256
#define KTOT 384  // CC + CF
#define NBLKF (NF / 128)

// ---------------- scratch (device globals; no allocations allowed) ----------
__device__ float g_Yc[BATCH * CO * NC];   // Wc @ Fc : [B, Co, Nc]
__device__ int   g_idx[BATCH * NF];
__device__ float g_ps [BATCH * CO * NBLKF];
__device__ float g_pss[BATCH * CO * NBLKF];
__device__ float g_scale[CO];
__device__ float g_shift[CO];

// ---------------- helpers ----------------------------------------------------
__device__ __forceinline__ uint32_t smem_u32(const void* p) {
    uint32_t a;
    asm("{ .reg .u64 t; cvta.to.shared.u64 t, %1; cvt.u32.u64 %0, t; }"
        : "=r"(a) : "l"(p));
    return a;
}

__device__ __forceinline__ void ldsm4(uint32_t (&r)[4], uint32_t addr) {
    asm volatile("ldmatrix.sync.aligned.m8n8.x4.shared.b16 {%0,%1,%2,%3}, [%4];"
                 : "=r"(r[0]), "=r"(r[1]), "=r"(r[2]), "=r"(r[3]) : "r"(addr));
}
__device__ __forceinline__ void ldsm4t(uint32_t (&r)[4], uint32_t addr) {
    asm volatile("ldmatrix.sync.aligned.m8n8.x4.trans.shared.b16 {%0,%1,%2,%3}, [%4];"
                 : "=r"(r[0]), "=r"(r[1]), "=r"(r[2]), "=r"(r[3]) : "r"(addr));
}
__device__ __forceinline__ void mma16816(float (&d)[4], const uint32_t (&a)[4],
                                         uint32_t b0, uint32_t b1) {
    asm volatile(
        "mma.sync.aligned.m16n8k16.row.col.f32.bf16.bf16.f32 "
        "{%0,%1,%2,%3}, {%4,%5,%6,%7}, {%8,%9}, {%0,%1,%2,%3};"
        : "+f"(d[0]), "+f"(d[1]), "+f"(d[2]), "+f"(d[3])
        : "r"(a[0]), "r"(a[1]), "r"(a[2]), "r"(a[3]), "r"(b0), "r"(b1));
}

// split two fp32 into packed-bf16x2 hi and lo words
__device__ __forceinline__ void split2(float x0, float x1, uint32_t& hi, uint32_t& lo) {
    __nv_bfloat16 h0 = __float2bfloat16(x0);
    __nv_bfloat16 h1 = __float2bfloat16(x1);
    float r0 = x0 - __bfloat162float(h0);
    float r1 = x1 - __bfloat162float(h1);
    __nv_bfloat162 hh;
    hh.x = h0; hh.y = h1;
    __nv_bfloat162 ll;
    ll.x = __float2bfloat16(r0); ll.y = __float2bfloat16(r1);
    hi = *(uint32_t*)&hh;
    lo = *(uint32_t*)&ll;
}

// ============================================================================
// K1: nearest coarse neighbor per fine point (unchanged, passing)
// ============================================================================
__global__ void nn_kernel(const float* __restrict__ xyzc,
                          const float* __restrict__ xyzf) {
    __shared__ float4 sc[2048];
    const int b = blockIdx.y;
    const int f = blockIdx.x * 128 + threadIdx.x;
    const float* p = xyzf + ((size_t)b * NF + f) * 3;
    const float px = -2.0f * p[0];
    const float py = -2.0f * p[1];
    const float pz = -2.0f * p[2];
    float best = 3.4e38f;
    int bi = 0;
    const float* xb = xyzc + (size_t)b * NC * 3;
    for (int half = 0; half < 2; half++) {
        for (int j = threadIdx.x; j < 2048; j += 128) {
            const float* c = xb + (size_t)(half * 2048 + j) * 3;
            float x = c[0], y = c[1], z = c[2];
            sc[j] = make_float4(x, y, z, x * x + y * y + z * z);
        }
        __syncthreads();
        const int base = half * 2048;
#pragma unroll 4
        for (int j = 0; j < 2048; j += 2) {
            float4 c0 = sc[j];
            float4 c1 = sc[j + 1];
            float d0 = fmaf(px, c0.x, c0.w);
            d0 = fmaf(py, c0.y, d0);
            d0 = fmaf(pz, c0.z, d0);
            float d1 = fmaf(px, c1.x, c1.w);
            d1 = fmaf(py, c1.y, d1);
            d1 = fmaf(pz, c1.z, d1);
            float m = fminf(d0, d1);
            if (m < best) {
                best = m;
                bi = (d0 <= d1) ? (base + j) : (base + j + 1);
            }
        }
        __syncthreads();
    }
    g_idx[b * NF + f] = bi;
}

// ============================================================================
// HMMA bf16 split GEMM:  out[b,m,n] = sum_k W[m, WOFF+k] * F[b,k,n]
// fp32 inputs converted to bf16 hi/lo while staging into smem;
// products hi*hi + hi*lo + lo*hi accumulated in fp32 via mma.m16n8k16.
// BM=BN=128, BK=32, 256 threads (8 warps, 4m x 2n), warp tile 32x64.
// GATHER: += g_Yc[b][m][idx[n]], write dout, fused BN partials. else -> g_Yc.
// ============================================================================
#define AROW 40     // A tile row stride (bf16 elems): 80 B
#define BROW 136    // B tile row stride (bf16 elems): 272 B
#define OFF_AH 0
#define OFF_AL 10240
#define OFF_BH 20480
#define OFF_BL 29184
#define OSTR 132    // epilogue smem float stride (16B-aligned rows)
#define SMEM_BYTES (128 * OSTR * 4)  // 67584 (covers tiles: 37888)

template <int N, int KDIM, int WOFF, bool GATHER>
__global__ __launch_bounds__(256) void hmma_gemm_kernel(
    const float* __restrict__ W, const float* __restrict__ F,
    float* __restrict__ dout) {
    extern __shared__ char smp[];
    const uint32_t sb = smem_u32(smp);
    __shared__ int sidx[128];

    const int b = blockIdx.z;
    const int mBase = blockIdx.y * 128;
    const int nBase = blockIdx.x * 128;
    const int t = threadIdx.x;
    const int w = t >> 5;
    const int lid = t & 31;
    const int wm = (w >> 1) * 32;  // warp m offset
    const int wn = (w & 1) * 64;   // warp n offset

    if (GATHER && t < 128) sidx[t] = g_idx[b * NF + nBase + t];

    float c[2][8][4];
#pragma unroll
    for (int mt = 0; mt < 2; mt++)
#pragma unroll
        for (int nt = 0; nt < 8; nt++)
#pragma unroll
            for (int r = 0; r < 4; r++) c[mt][nt][r] = 0.f;

    const float* Wp = W + (size_t)mBase * KTOT + WOFF;
    const float* Fp = F + (size_t)b * KDIM * N + nBase;

    // ldmatrix lane addresses (byte offsets within tiles)
    const int a_row = (lid & 7) + ((lid >> 3) & 1) * 8;   // m within 16
    const int a_colb = (lid >> 4) * 8;                    // k 8-block
    const int b_row = (lid & 7) + ((lid >> 3) & 1) * 8;   // k within 16
    const int b_colb = (lid >> 4) * 8;                    // n 8-block

    for (int k0 = 0; k0 < KDIM; k0 += 32) {
        __syncthreads();
        // ---- stage A tile: W[mBase+m][WOFF+k0+k], m 0..127, k 0..31
        {
            const int kq = (t & 7) * 4;
            const int m0 = t >> 3;  // 0..31
#pragma unroll
            for (int p = 0; p < 4; p++) {
                const int m = m0 + 32 * p;
                float4 v = *(const float4*)&Wp[(size_t)m * KTOT + k0 + kq];
                uint32_t h0, l0, h1, l1;
                split2(v.x, v.y, h0, l0);
                split2(v.z, v.w, h1, l1);
                char* dst = smp + (m * AROW + kq) * 2;
                *(uint2*)(dst + OFF_AH) = make_uint2(h0, h1);
                *(uint2*)(dst + OFF_AL) = make_uint2(l0, l1);
            }
        }
        // ---- stage B tile: F[k0+k][nBase+n], k 0..31, n 0..127
        {
            const int n4 = (t & 31) * 4;
            const int kk0 = t >> 5;  // 0..7
#pragma unroll
            for (int p = 0; p < 4; p++) {
                const int k = kk0 + 8 * p;
                float4 v = *(const float4*)&Fp[(size_t)(k0 + k) * N + n4];
                uint32_t h0, l0, h1, l1;
                split2(v.x, v.y, h0, l0);
                split2(v.z, v.w, h1, l1);
                char* dst = smp + (k * BROW + n4) * 2;
                *(uint2*)(dst + OFF_BH) = make_uint2(h0, h1);
                *(uint2*)(dst + OFF_BL) = make_uint2(l0, l1);
            }
        }
        __syncthreads();

#pragma unroll
        for (int k16 = 0; k16 < 2; k16++) {
            uint32_t ah[2][4], al[2][4], bh[4][4], bl[4][4];
#pragma unroll
            for (int mt = 0; mt < 2; mt++) {
                uint32_t ad = sb +
                    ((wm + mt * 16 + a_row) * AROW + k16 * 16 + a_colb) * 2;
                ldsm4(ah[mt], ad + OFF_AH);
                ldsm4(al[mt], ad + OFF_AL);
            }
#pragma unroll
            for (int ng = 0; ng < 4; ng++) {
                uint32_t bd = sb +
                    ((k16 * 16 + b_row) * BROW + wn + ng * 16 + b_colb) * 2;
                ldsm4t(bh[ng], bd + OFF_BH);
                ldsm4t(bl[ng], bd + OFF_BL);
            }
#pragma unroll
            for (int mt = 0; mt < 2; mt++)
#pragma unroll
                for (int nt = 0; nt < 8; nt++) {
                    const int ng = nt >> 1;
                    const int pr = (nt & 1) * 2;
                    mma16816(c[mt][nt], ah[mt], bh[ng][pr], bh[ng][pr + 1]);
                    mma16816(c[mt][nt], ah[mt], bl[ng][pr], bl[ng][pr + 1]);
                    mma16816(c[mt][nt], al[mt], bh[ng][pr], bh[ng][pr + 1]);
                }
        }
    }

    // ---- epilogue: accum -> smem [128][OSTR] -> coalesced global
    __syncthreads();
    float* smOut = (float*)smp;
    {
        const int r_m = lid >> 2;          // row within m8
        const int cn = (lid & 3) * 2;      // col pair within n8
#pragma unroll
        for (int mt = 0; mt < 2; mt++)
#pragma unroll
            for (int nt = 0; nt < 8; nt++) {
                const int row = wm + mt * 16 + r_m;
                const int col = wn + nt * 8 + cn;
                *(float2*)&smOut[row * OSTR + col] =
                    make_float2(c[mt][nt][0], c[mt][nt][1]);
                *(float2*)&smOut[(row + 8) * OSTR + col] =
                    make_float2(c[mt][nt][2], c[mt][nt][3]);
            }
    }
    __syncthreads();

#pragma unroll 4
    for (int rr = 0; rr < 16; rr++) {
        const int r0 = w + rr * 8;  // 0..127
        const int m = mBase + r0;
        float4 v = *(float4*)&smOut[r0 * OSTR + lid * 4];
        if (GATHER) {
            const float* yc = g_Yc + ((size_t)b * CO + m) * NC;
            v.x += yc[sidx[lid * 4 + 0]];
            v.y += yc[sidx[lid * 4 + 1]];
            v.z += yc[sidx[lid * 4 + 2]];
            v.w += yc[sidx[lid * 4 + 3]];
            *(float4*)&dout[((size_t)b * CO + m) * NF + nBase + lid * 4] = v;
            float s = v.x + v.y + v.z + v.w;
            float ss = v.x * v.x + v.y * v.y + v.z * v.z + v.w * v.w;
#pragma unroll
            for (int off = 16; off > 0; off >>= 1) {
                s += __shfl_down_sync(0xffffffffu, s, off);
                ss += __shfl_down_sync(0xffffffffu, ss, off);
            }
            if (lid == 0) {
                g_ps [((size_t)b * CO + m) * NBLKF + blockIdx.x] = s;
                g_pss[((size_t)b * CO + m) * NBLKF + blockIdx.x] = ss;
            }
        } else {
            *(float4*)&g_Yc[((size_t)b * CO + m) * NC + nBase + lid * 4] = v;
        }
    }
}

// ============================================================================
// K4: finish BN stats from partials (unchanged)
// ============================================================================
__global__ void stats2_kernel(const float* __restrict__ gamma,
                              const float* __restrict__ beta) {
    const int o = blockIdx.x * 8 + (threadIdx.x >> 5);
    const int lane = threadIdx.x & 31;
    float s = 0.f, ss = 0.f;
#pragma unroll
    for (int j = 0; j < 8; j++) {
        int p = lane + j * 32;
        int b = p >> 7;
        int nblk = p & 127;
        size_t off = ((size_t)b * CO + o) * NBLKF + nblk;
        s += g_ps[off];
        ss += g_pss[off];
    }
#pragma unroll
    for (int off = 16; off > 0; off >>= 1) {
        s += __shfl_down_sync(0xffffffffu, s, off);
        ss += __shfl_down_sync(0xffffffffu, ss, off);
    }
    if (lane == 0) {
        const float invn = 1.0f / (BATCH * NF);
        float mean = s * invn;
        float var = ss * invn - mean * mean;
        var = fmaxf(var, 0.0f);
        float r = rsqrtf(var + 1e-5f);
        float sc = gamma[o] * r;
        g_scale[o] = sc;
        g_shift[o] = beta[o] - mean * sc;
    }
}

// ============================================================================
// K5: y = relu(y * scale + shift) in place (unchanged)
// ============================================================================
__global__ void norm_kernel(float* __restrict__ y) {
    const size_t i = (size_t)blockIdx.x * blockDim.x + threadIdx.x;
    const int o = (int)((i >> 12) & (CO - 1));
    const float sc = g_scale[o];
    const float sh = g_shift[o];
    float4 v = ((const float4*)y)[i];
    v.x = fmaxf(fmaf(v.x, sc, sh), 0.0f);
    v.y = fmaxf(fmaf(v.y, sc, sh), 0.0f);
    v.z = fmaxf(fmaf(v.z, sc, sh), 0.0f);
    v.w = fmaxf(fmaf(v.w, sc, sh), 0.0f);
    ((float4*)y)[i] = v;
}

// ============================================================================
extern "C" void kernel_launch(void* const* d_in, const int* in_sizes, int n_in,
                              void* d_out, int out_size) {
    const float* xyzc  = (const float*)d_in[0];  // [2, 4096, 3]
    const float* fc    = (const float*)d_in[1];  // [2, 256, 4096]
    const float* xyzf  = (const float*)d_in[2];  // [2, 16384, 3]
    const float* ff    = (const float*)d_in[3];  // [2, 128, 16384]
    const float* W     = (const float*)d_in[4];  // [256, 384]
    const float* gamma = (const float*)d_in[5];  // [256]
    const float* beta  = (const float*)d_in[6];  // [256]
    float* out = (float*)d_out;                  // [2, 256, 16384]

    (void)in_sizes; (void)n_in; (void)out_size;

    static bool attr_done = false;
    if (!attr_done) {
        cudaFuncSetAttribute(hmma_gemm_kernel<NC, CC, 0, false>,
                             cudaFuncAttributeMaxDynamicSharedMemorySize, SMEM_BYTES);
        cudaFuncSetAttribute(hmma_gemm_kernel<NF, CF, CC, true>,
                             cudaFuncAttributeMaxDynamicSharedMemorySize, SMEM_BYTES);
        attr_done = true;
    }

    nn_kernel<<<dim3(NF / 128, BATCH), 128>>>(xyzc, xyzf);

    // Yc = Wc @ Fc   (tensor cores, bf16 split)
    hmma_gemm_kernel<NC, CC, 0, false>
        <<<dim3(NC / 128, CO / 128, BATCH), 256, SMEM_BYTES>>>(W, fc, out);

    // y = Wf @ Ff + gather(Yc)   (tensor cores, fused BN partials)
    hmma_gemm_kernel<NF, CF, CC, true>
        <<<dim3(NF / 128, CO / 128, BATCH), 256, SMEM_BYTES>>>(W, ff, out);

    stats2_kernel<<<CO / 8, 256>>>(gamma, beta);
    norm_kernel<<<(BATCH * CO * NF / 4) / 256, 256>>>(out);
}